// round 16
// baseline (speedup 1.0000x reference)
#include <cuda_runtime.h>
#include <math.h>

// ---------------------------------------------------------------------------
// TnoInvTime: Toeplitz neural operator via shared-memory FFT (N=4096, M=2N=8192)
//   B=2, H=8, N=4096, D=64, RPE=64, LAYERS=3
// ---------------------------------------------------------------------------

#define MM 8192            // FFT length (2n)
#define NSEQ 4096
#define PAD(i) ((i) + ((i) >> 3))   // smem bank-conflict padding (injective)

// scratch
__device__ float  g_G[8192 * 64];             // final MLP activations (2 MB)
__device__ float  g_A[512 * 8192];            // a transposed [channel][t] (16.8 MB)
__device__ float4 g_PQ[256 * 8192];           // packed spectra (33.6 MB)

// ------------------------------ f32x2 helpers ------------------------------
typedef unsigned long long u64;
__device__ __forceinline__ u64 f2pack(float x, float y) {
  u64 r; asm("mov.b64 %0, {%1, %2};" : "=l"(r) : "f"(x), "f"(y)); return r;
}
__device__ __forceinline__ float2 f2unpack(u64 v) {
  float2 r; asm("mov.b64 {%0, %1}, %2;" : "=f"(r.x), "=f"(r.y) : "l"(v)); return r;
}
__device__ __forceinline__ u64 f2fma(u64 a, u64 b, u64 c) {
  u64 d; asm("fma.rn.f32x2 %0, %1, %2, %3;" : "=l"(d) : "l"(a), "l"(b), "l"(c)); return d;
}

// ------------------------------ complex helpers ----------------------------
__device__ __forceinline__ float2 cadd(float2 a, float2 b){ return make_float2(a.x+b.x, a.y+b.y); }
__device__ __forceinline__ float2 csub(float2 a, float2 b){ return make_float2(a.x-b.x, a.y-b.y); }
__device__ __forceinline__ float2 cmul(float2 a, float2 b){
  return make_float2(fmaf(a.x, b.x, -a.y*b.y), fmaf(a.x, b.y, a.y*b.x));
}
__device__ __forceinline__ float2 mul_mi(float2 a){ return make_float2(a.y, -a.x); } // *(-i)

// 8-point DFT (DIF, natural-order output)
__device__ __forceinline__ void dft8(const float2* a, float2* b) {
  const float S = 0.70710678118654752440f;
  float2 u0 = cadd(a[0], a[4]), l0 = csub(a[0], a[4]);
  float2 u1 = cadd(a[1], a[5]), l1 = csub(a[1], a[5]);
  float2 u2 = cadd(a[2], a[6]), l2 = csub(a[2], a[6]);
  float2 u3 = cadd(a[3], a[7]), l3 = csub(a[3], a[7]);
  l1 = make_float2(S*(l1.x + l1.y), S*(l1.y - l1.x));
  l2 = mul_mi(l2);
  l3 = make_float2(S*(l3.y - l3.x), -S*(l3.x + l3.y));
  float2 p0 = cadd(u0, u2), q0 = csub(u0, u2);
  float2 p1 = cadd(u1, u3), q1 = mul_mi(csub(u1, u3));
  b[0] = cadd(p0, p1); b[4] = csub(p0, p1);
  b[2] = cadd(q0, q1); b[6] = csub(q0, q1);
  float2 r0 = cadd(l0, l2), s0 = csub(l0, l2);
  float2 r1 = cadd(l1, l3), s1 = mul_mi(csub(l1, l3));
  b[1] = cadd(r0, r1); b[5] = csub(r0, r1);
  b[3] = cadd(s0, s1); b[7] = csub(s0, s1);
}

// 8-point DFT when a[4..7] == 0 (zero-padded input): u_j = l_j = a[j]
__device__ __forceinline__ void dft8_zh(const float2* a, float2* b) {
  const float S = 0.70710678118654752440f;
  float2 u0 = a[0], u1 = a[1], u2 = a[2], u3 = a[3];
  float2 l0 = a[0];
  float2 l1 = make_float2(S*(a[1].x + a[1].y), S*(a[1].y - a[1].x));
  float2 l2 = mul_mi(a[2]);
  float2 l3 = make_float2(S*(a[3].y - a[3].x), -S*(a[3].x + a[3].y));
  float2 p0 = cadd(u0, u2), q0 = csub(u0, u2);
  float2 p1 = cadd(u1, u3), q1 = mul_mi(csub(u1, u3));
  b[0] = cadd(p0, p1); b[4] = csub(p0, p1);
  b[2] = cadd(q0, q1); b[6] = csub(q0, q1);
  float2 r0 = cadd(l0, l2), s0 = csub(l0, l2);
  float2 r1 = cadd(l1, l3), s1 = mul_mi(csub(l1, l3));
  b[1] = cadd(r0, r1); b[5] = csub(r0, r1);
  b[3] = cadd(s0, s1); b[7] = csub(s0, s1);
}

// One Stockham radix-8 stage; ZH = upper half of input is zero (skip loads).
template<int S_, int LS, bool ZH>
__device__ __forceinline__ void stage8(const float2* __restrict__ src,
                                       float2* __restrict__ dst,
                                       const float2* __restrict__ tab, int tid) {
#pragma unroll
  for (int it = 0; it < 2; ++it) {           // 1024 items / 512 threads
    int w = tid + it * 512;
    int p = w >> LS;
    int q = w & (S_ - 1);
    float2 a[8], b[8];
    if (ZH) {
#pragma unroll
      for (int j = 0; j < 4; ++j) a[j] = src[PAD(w + j * 1024)];
      dft8_zh(a, b);
    } else {
#pragma unroll
      for (int j = 0; j < 8; ++j) a[j] = src[PAD(w + j * 1024)];
      dft8(a, b);
    }
    float2 tw = tab[p * S_];
    int ob = q + ((p << 3) * S_);
    dst[PAD(ob)] = b[0];
    float2 wk = tw;
    dst[PAD(ob + S_)] = cmul(b[1], wk);
#pragma unroll
    for (int k = 2; k < 8; ++k) {
      wk = cmul(wk, tw);
      dst[PAD(ob + k * S_)] = cmul(b[k], wk);
    }
  }
}

// 4 radix-8 stages: A -> B -> A -> B -> A (result in A). Ends with sync.
template<bool ZH>
__device__ __forceinline__ void fft_stages(float2* A, float2* B, const float2* tab, int tid) {
  stage8<1,   0, ZH   >(A, B, tab, tid); __syncthreads();
  stage8<8,   3, false>(B, A, tab, tid); __syncthreads();
  stage8<64,  6, false>(A, B, tab, tid); __syncthreads();
  stage8<512, 9, false>(B, A, tab, tid); __syncthreads();
}

// final radix-2 stage, full output: A -> B. Ends with sync.
__device__ __forceinline__ void radix2_full(const float2* A, float2* B, int tid) {
#pragma unroll
  for (int it = 0; it < 8; ++it) {
    int w = tid + it * 512;
    float2 a = A[PAD(w)], b = A[PAD(w + 4096)];
    B[PAD(w)]        = cadd(a, b);
    B[PAD(w + 4096)] = csub(a, b);
  }
  __syncthreads();
}

// --------------------- kernel 0a: hidden MLP layers ------------------------
// 256 CTAs x 128 threads. Warp handles 8 positions concurrently; lane owns
// channels (lane, lane+32). Matmuls read g via smem broadcast (float4), not
// shuffle chains. Writes final activations G[8192][64] to global.
__global__ __launch_bounds__(128)
void k_hidden(const float* __restrict__ w_in,  const float* __restrict__ b_in,
              const float* __restrict__ w_hid, const float* __restrict__ b_hid) {
  extern __shared__ __align__(16) char sraw[];
  float* sWh = (float*)sraw;              // 12288 floats
  float* sG  = sWh + 12288;               // 4 warps * 8 pos * 68

  int tid = threadIdx.x;
  for (int i = tid; i < 3072; i += 128)
    ((float4*)sWh)[i] = ((const float4*)w_hid)[i];
  __syncthreads();

  int warp = tid >> 5, lane = tid & 31;
  float* gW = sG + warp * (8 * 68);
  int t0 = (blockIdx.x * 4 + warp) * 8;

  float wi0 = w_in[lane], wi1 = w_in[lane + 32];
  float bi0 = b_in[lane], bi1 = b_in[lane + 32];

  float h0[8], h1[8];
#pragma unroll
  for (int p = 0; p < 8; ++p) {
    int t = t0 + p;
    float idxv;
    if (t == 0 || t == 4096) idxv = 1.0f;
    else if (t < 4096)       idxv = 1.0f / (float)(t + 1);
    else                     idxv = -1.0f / (float)(8193 - t);
    h0[p] = fmaf(idxv, wi0, bi0);
    h1[p] = fmaf(idxv, wi1, bi1);
  }

  for (int l = 0; l < 3; ++l) {
    float ss[8];
#pragma unroll
    for (int p = 0; p < 8; ++p) ss[p] = h0[p]*h0[p] + h1[p]*h1[p];
#pragma unroll
    for (int off = 16; off; off >>= 1)
#pragma unroll
      for (int p = 0; p < 8; ++p) ss[p] += __shfl_xor_sync(0xffffffffu, ss[p], off);
#pragma unroll
    for (int p = 0; p < 8; ++p) {
      float sc = rsqrtf(ss[p] * (1.0f/64.0f) + 1e-8f);
      gW[p*68 + lane]      = fmaxf(h0[p] * sc, 0.0f);
      gW[p*68 + lane + 32] = fmaxf(h1[p] * sc, 0.0f);
    }
    __syncwarp();

    float a0[8], a1[8];
    float bh0 = b_hid[l*64 + lane], bh1 = b_hid[l*64 + lane + 32];
#pragma unroll
    for (int p = 0; p < 8; ++p) { a0[p] = bh0; a1[p] = bh1; }
    const float* Wl = sWh + l * 4096;
    for (int i4 = 0; i4 < 16; ++i4) {
      float4 gv[8];
#pragma unroll
      for (int p = 0; p < 8; ++p) gv[p] = *(const float4*)&gW[p*68 + i4*4];
#pragma unroll
      for (int kk = 0; kk < 4; ++kk) {
        int i = i4*4 + kk;
        float wa = Wl[i*64 + lane], wb = Wl[i*64 + lane + 32];
#pragma unroll
        for (int p = 0; p < 8; ++p) {
          float g = (kk == 0) ? gv[p].x : (kk == 1) ? gv[p].y : (kk == 2) ? gv[p].z : gv[p].w;
          a0[p] = fmaf(g, wa, a0[p]);
          a1[p] = fmaf(g, wb, a1[p]);
        }
      }
    }
#pragma unroll
    for (int p = 0; p < 8; ++p) { h0[p] = a0[p]; h1[p] = a1[p]; }
    __syncwarp();
  }

  // final rms+relu -> G
  float ss[8];
#pragma unroll
  for (int p = 0; p < 8; ++p) ss[p] = h0[p]*h0[p] + h1[p]*h1[p];
#pragma unroll
  for (int off = 16; off; off >>= 1)
#pragma unroll
    for (int p = 0; p < 8; ++p) ss[p] += __shfl_xor_sync(0xffffffffu, ss[p], off);
#pragma unroll
  for (int p = 0; p < 8; ++p) {
    float sc = rsqrtf(ss[p] * (1.0f/64.0f) + 1e-8f);
    g_G[(size_t)(t0 + p)*64 + lane]      = fmaxf(h0[p] * sc, 0.0f);
    g_G[(size_t)(t0 + p)*64 + lane + 32] = fmaxf(h1[p] * sc, 0.0f);
  }
}

// --------------------- kernel 0b: output GEMM (f32x2) ----------------------
// A[8192][512] = G @ w_out + b_out, written transposed into g_A[ch][t].
// Grid (64, 4): 128-position x 128-channel tiles. Thread = 8 pos x 8 ch,
// channel-pairs packed as f32x2 (weights contiguous -> no weight splats).
__global__ __launch_bounds__(256)
void k_out(const float* __restrict__ w_out, const float* __restrict__ b_out) {
  extern __shared__ __align__(16) char sraw[];
  float* Gs = (float*)sraw;       // 128 x 64, XOR-swizzled float4 columns
  float* Ws = Gs + 128*64;        // 64 x 128

  int tid = threadIdx.x;
  int T0 = blockIdx.x * 128;
  int C0 = blockIdx.y * 128;

  for (int i = tid; i < 128*16; i += 256) {
    int p = i >> 4, kq = i & 15;
    float4 v = *(const float4*)&g_G[(size_t)(T0 + p)*64 + kq*4];
    int sw = (kq ^ (p >> 3)) & 15;
    *(float4*)&Gs[p*64 + sw*4] = v;
  }
  for (int i = tid; i < 64*32; i += 256) {
    int k = i >> 5, cq = i & 31;
    *(float4*)&Ws[k*128 + cq*4] = *(const float4*)&w_out[(size_t)k*512 + C0 + cq*4];
  }
  __syncthreads();

  int pb  = (tid & 15) * 8;
  int cb  = (tid >> 4) * 8;
  int swb = tid & 15;

  u64 acc[4][8];
  {
    float4 bA = *(const float4*)&b_out[C0 + cb];
    float4 bB = *(const float4*)&b_out[C0 + cb + 4];
    u64 b01 = f2pack(bA.x, bA.y), b23 = f2pack(bA.z, bA.w);
    u64 b45 = f2pack(bB.x, bB.y), b67 = f2pack(bB.z, bB.w);
#pragma unroll
    for (int p = 0; p < 8; ++p) { acc[0][p]=b01; acc[1][p]=b23; acc[2][p]=b45; acc[3][p]=b67; }
  }

  for (int k4 = 0; k4 < 16; ++k4) {
    float4 gq[8];
    int col = ((k4 ^ swb) & 15) * 4;
#pragma unroll
    for (int p = 0; p < 8; ++p) gq[p] = *(const float4*)&Gs[(pb + p)*64 + col];
#pragma unroll
    for (int kk = 0; kk < 4; ++kk) {
      const float* wr = &Ws[(k4*4 + kk)*128 + cb];
      float4 wA = *(const float4*)wr;
      float4 wB = *(const float4*)(wr + 4);
      u64 w01 = f2pack(wA.x, wA.y), w23 = f2pack(wA.z, wA.w);
      u64 w45 = f2pack(wB.x, wB.y), w67 = f2pack(wB.z, wB.w);
#pragma unroll
      for (int p = 0; p < 8; ++p) {
        float g = (kk == 0) ? gq[p].x : (kk == 1) ? gq[p].y : (kk == 2) ? gq[p].z : gq[p].w;
        u64 gs = f2pack(g, g);
        acc[0][p] = f2fma(gs, w01, acc[0][p]);
        acc[1][p] = f2fma(gs, w23, acc[1][p]);
        acc[2][p] = f2fma(gs, w45, acc[2][p]);
        acc[3][p] = f2fma(gs, w67, acc[3][p]);
      }
    }
  }

#pragma unroll
  for (int cp = 0; cp < 4; ++cp) {
    float2 u[8];
#pragma unroll
    for (int p = 0; p < 8; ++p) u[p] = f2unpack(acc[cp][p]);
    size_t row0 = (size_t)(C0 + cb + 2*cp) * MM + T0 + pb;
    *(float4*)&g_A[row0]     = make_float4(u[0].x, u[1].x, u[2].x, u[3].x);
    *(float4*)&g_A[row0 + 4] = make_float4(u[4].x, u[5].x, u[6].x, u[7].x);
    size_t row1 = row0 + MM;
    *(float4*)&g_A[row1]     = make_float4(u[0].y, u[1].y, u[2].y, u[3].y);
    *(float4*)&g_A[row1 + 4] = make_float4(u[4].y, u[5].y, u[6].y, u[7].y);
  }
}

// --------------------- kernel 1: FFT of a, build P/Q -----------------------
__global__ __launch_bounds__(512, 1)
void k_afft() {
  extern __shared__ __align__(16) char sraw[];
  float2* A   = (float2*)sraw;
  float2* B   = A + 9216;
  float2* tab = B + 9216;
  int tid = threadIdx.x;
  int h  = blockIdx.x >> 5;
  int dp = blockIdx.x & 31;

  const float* r0 = g_A + (size_t)(h * 64 + dp * 2) * MM;
  const float* r1 = r0 + MM;
  for (int t = tid; t < MM; t += 512) A[PAD(t)] = make_float2(r0[t], r1[t]);
  for (int k = tid; k < 1024; k += 512) {
    float s, c; sincospif(-(float)k * (1.0f/4096.0f), &s, &c);
    tab[k] = make_float2(c, s);
  }
  __syncthreads();
  fft_stages<false>(A, B, tab, tid);
  radix2_full(A, B, tid);

  float4* pq = g_PQ + (size_t)(h * 32 + dp) * MM;
  for (int k = tid; k < MM; k += 512) {
    float2 u  = B[PAD(k)];
    float2 v  = B[PAD((MM - k) & (MM - 1))];
    float2 vc = make_float2(v.x, -v.y);
    float2 Sm = cadd(u, vc), Dv = csub(u, vc);
    pq[k] = make_float4(0.25f*(Sm.x + Dv.y), 0.25f*(Sm.y - Dv.x),
                        0.25f*(Sm.x - Dv.y), 0.25f*(Sm.y + Dv.x));
  }
}

// ----------------- kernel 2: FFT conv per (b, h, dpair) --------------------
__global__ __launch_bounds__(512, 1)
void k_conv(const float* __restrict__ x, float* __restrict__ out) {
  extern __shared__ __align__(16) char sraw[];
  float2* A   = (float2*)sraw;
  float2* B   = A + 9216;
  float2* tab = B + 9216;
  int tid = threadIdx.x;
  int b   = blockIdx.x >> 8;
  int rem = blockIdx.x & 255;
  int h   = rem >> 5;
  int dp  = rem & 31;

  const float* xb = x + ((size_t)(b * 8 + h) * NSEQ) * 64 + dp * 2;
  for (int j = tid; j < NSEQ; j += 512)
    A[PAD(j)] = *(const float2*)(xb + (size_t)j * 64);
  // upper half implicitly zero: first stage uses dft8_zh and never reads it
  for (int k = tid; k < 1024; k += 512) {
    float s, c; sincospif(-(float)k * (1.0f/4096.0f), &s, &c);
    tab[k] = make_float2(c, s);
  }
  __syncthreads();

  fft_stages<true>(A, B, tab, tid);              // forward (zero-padded input)
  radix2_full(A, B, tid);                        // Z in B

  const float4* pq = g_PQ + (size_t)(h * 32 + dp) * MM;
  for (int k = tid; k < MM; k += 512) {
    float2 z   = B[PAD(k)];
    float2 zr  = B[PAD((MM - k) & (MM - 1))];
    float4 c4  = pq[k];
    float2 P   = make_float2(c4.x, c4.y);
    float2 Q   = make_float2(c4.z, c4.w);
    float2 zrc = make_float2(zr.x, -zr.y);
    float2 W   = cadd(cmul(P, z), cmul(Q, zrc)); // spectrum of y_d + i*y_e
    A[PAD(k)]  = make_float2(W.x, -W.y);         // conj for inverse-via-forward
  }
  __syncthreads();

  fft_stages<false>(A, B, tab, tid);             // inverse stages 1-4, result in A

  // fused final radix-2 + output: only lower 4096 needed
  float* ob = out + ((size_t)(b * 8 + h) * NSEQ) * 64 + dp * 2;
  const float inv = 1.0f / (float)MM;
#pragma unroll
  for (int it = 0; it < 8; ++it) {
    int w = tid + it * 512;
    float2 s = cadd(A[PAD(w)], A[PAD(w + 4096)]);
    *(float2*)(ob + (size_t)w * 64) = make_float2(s.x * inv, -s.y * inv);
  }
}

// ------------------------------ launch -------------------------------------
extern "C" void kernel_launch(void* const* d_in, const int* in_sizes, int n_in,
                              void* d_out, int out_size) {
  const float* x     = (const float*)d_in[0];
  const float* w_in  = (const float*)d_in[1];
  const float* b_in  = (const float*)d_in[2];
  const float* w_hid = (const float*)d_in[3];
  const float* b_hid = (const float*)d_in[4];
  const float* w_out = (const float*)d_in[5];
  const float* b_out = (const float*)d_in[6];
  float* out = (float*)d_out;

  const size_t smemH = (size_t)(12288 + 4 * 8 * 68) * sizeof(float);          //  57,856 B
  const size_t smemO = (size_t)(128*64 + 64*128) * sizeof(float);             //  65,536 B
  const size_t smemF = (size_t)(2 * 9216 + 1024) * sizeof(float2);            // 155,648 B
  cudaFuncSetAttribute(k_hidden, cudaFuncAttributeMaxDynamicSharedMemorySize, (int)smemH);
  cudaFuncSetAttribute(k_out,    cudaFuncAttributeMaxDynamicSharedMemorySize, (int)smemO);
  cudaFuncSetAttribute(k_afft,   cudaFuncAttributeMaxDynamicSharedMemorySize, (int)smemF);
  cudaFuncSetAttribute(k_conv,   cudaFuncAttributeMaxDynamicSharedMemorySize, (int)smemF);

  k_hidden<<<256, 128, smemH>>>(w_in, b_in, w_hid, b_hid);
  k_out   <<<dim3(64, 4), 256, smemO>>>(w_out, b_out);
  k_afft  <<<256, 512, smemF>>>();
  k_conv  <<<512, 512, smemF>>>(x, out);
}

// round 17
// speedup vs baseline: 1.2639x; 1.2639x over previous
#include <cuda_runtime.h>
#include <math.h>

// ---------------------------------------------------------------------------
// TnoInvTime: Toeplitz neural operator via shared-memory FFT (N=4096, M=2N=8192)
//   B=2, H=8, N=4096, D=64, RPE=64, LAYERS=3
// Radix-16 Stockham (16^3 * 2), fused radix-2+pointwise passes.
// ---------------------------------------------------------------------------

#define MM 8192            // FFT length (2n)
#define NSEQ 4096
#define PAD(i) ((i) + ((i) >> 4))   // smem padding (injective, LDS.64-phase conflict-free)
#define FBUF 8704                   // float2 slots per FFT buffer (PAD(8191)=8702)

// scratch
__device__ float  g_G[8192 * 64];             // final MLP activations (2 MB)
__device__ float  g_A[512 * 8192];            // a transposed [channel][t] (16.8 MB)
__device__ float4 g_PQ[256 * 8192];           // packed spectra (33.6 MB)

// ------------------------------ f32x2 helpers ------------------------------
typedef unsigned long long u64;
__device__ __forceinline__ u64 f2pack(float x, float y) {
  u64 r; asm("mov.b64 %0, {%1, %2};" : "=l"(r) : "f"(x), "f"(y)); return r;
}
__device__ __forceinline__ float2 f2unpack(u64 v) {
  float2 r; asm("mov.b64 {%0, %1}, %2;" : "=f"(r.x), "=f"(r.y) : "l"(v)); return r;
}
__device__ __forceinline__ u64 f2fma(u64 a, u64 b, u64 c) {
  u64 d; asm("fma.rn.f32x2 %0, %1, %2, %3;" : "=l"(d) : "l"(a), "l"(b), "l"(c)); return d;
}

// ------------------------------ complex helpers ----------------------------
__device__ __forceinline__ float2 cadd(float2 a, float2 b){ return make_float2(a.x+b.x, a.y+b.y); }
__device__ __forceinline__ float2 csub(float2 a, float2 b){ return make_float2(a.x-b.x, a.y-b.y); }
__device__ __forceinline__ float2 cmul(float2 a, float2 b){
  return make_float2(fmaf(a.x, b.x, -a.y*b.y), fmaf(a.x, b.y, a.y*b.x));
}
__device__ __forceinline__ float2 conjf2(float2 a){ return make_float2(a.x, -a.y); }
__device__ __forceinline__ float2 mul_mi(float2 a){ return make_float2(a.y, -a.x); } // *(-i)

// 8-point DFT (DIF, natural-order output)
__device__ __forceinline__ void dft8(const float2* a, float2* b) {
  const float S = 0.70710678118654752440f;
  float2 u0 = cadd(a[0], a[4]), l0 = csub(a[0], a[4]);
  float2 u1 = cadd(a[1], a[5]), l1 = csub(a[1], a[5]);
  float2 u2 = cadd(a[2], a[6]), l2 = csub(a[2], a[6]);
  float2 u3 = cadd(a[3], a[7]), l3 = csub(a[3], a[7]);
  l1 = make_float2(S*(l1.x + l1.y), S*(l1.y - l1.x));
  l2 = mul_mi(l2);
  l3 = make_float2(S*(l3.y - l3.x), -S*(l3.x + l3.y));
  float2 p0 = cadd(u0, u2), q0 = csub(u0, u2);
  float2 p1 = cadd(u1, u3), q1 = mul_mi(csub(u1, u3));
  b[0] = cadd(p0, p1); b[4] = csub(p0, p1);
  b[2] = cadd(q0, q1); b[6] = csub(q0, q1);
  float2 r0 = cadd(l0, l2), s0 = csub(l0, l2);
  float2 r1 = cadd(l1, l3), s1 = mul_mi(csub(l1, l3));
  b[1] = cadd(r0, r1); b[5] = csub(r0, r1);
  b[3] = cadd(s0, s1); b[7] = csub(s0, s1);
}

// 16-point DFT (DIF, natural-order output): b[k] = sum_j a[j] w16^(jk)
__device__ __forceinline__ void dft16(const float2* a, float2* b) {
  const float C1 = 0.92387953251128675613f;  // cos(pi/8)
  const float S1 = 0.38268343236508977173f;  // sin(pi/8)
  const float S  = 0.70710678118654752440f;
  float2 u[8], l[8];
#pragma unroll
  for (int j = 0; j < 8; ++j) { u[j] = cadd(a[j], a[j+8]); l[j] = csub(a[j], a[j+8]); }
  l[1] = cmul(l[1], make_float2( C1, -S1));
  l[2] = make_float2(S*(l[2].x + l[2].y), S*(l[2].y - l[2].x));
  l[3] = cmul(l[3], make_float2( S1, -C1));
  l[4] = mul_mi(l[4]);
  l[5] = cmul(l[5], make_float2(-S1, -C1));
  l[6] = make_float2(S*(l[6].y - l[6].x), -S*(l[6].x + l[6].y));
  l[7] = cmul(l[7], make_float2(-C1, -S1));
  float2 be[8], bo[8];
  dft8(u, be); dft8(l, bo);
#pragma unroll
  for (int m = 0; m < 8; ++m) { b[2*m] = be[m]; b[2*m+1] = bo[m]; }
}

// 16-point DFT when a[8..15] == 0: u_j = a[j], l_j = a[j]*w16^j
__device__ __forceinline__ void dft16_zh(const float2* a, float2* b) {
  const float C1 = 0.92387953251128675613f;
  const float S1 = 0.38268343236508977173f;
  const float S  = 0.70710678118654752440f;
  float2 l[8];
  l[0] = a[0];
  l[1] = cmul(a[1], make_float2( C1, -S1));
  l[2] = make_float2(S*(a[2].x + a[2].y), S*(a[2].y - a[2].x));
  l[3] = cmul(a[3], make_float2( S1, -C1));
  l[4] = mul_mi(a[4]);
  l[5] = cmul(a[5], make_float2(-S1, -C1));
  l[6] = make_float2(S*(a[6].y - a[6].x), -S*(a[6].x + a[6].y));
  l[7] = cmul(a[7], make_float2(-C1, -S1));
  float2 be[8], bo[8];
  dft8(a, be); dft8(l, bo);
#pragma unroll
  for (int m = 0; m < 8; ++m) { b[2*m] = be[m]; b[2*m+1] = bo[m]; }
}

// One Stockham radix-16 stage (512 items, one per thread).
// item w: p = w>>LS, q = w&(S_-1); loads src[w + j*512];
// stores dst[q + (16p+k)*S_] = b_k * w_8192^(S_*p*k).
template<int S_, int LS, bool ZH>
__device__ __forceinline__ void stage16(const float2* __restrict__ src,
                                        float2* __restrict__ dst,
                                        const float2* __restrict__ tab, int tid) {
  int w = tid;
  int p = w >> LS;
  int q = w & (S_ - 1);
  float2 a[16], b[16];
  if (ZH) {
#pragma unroll
    for (int j = 0; j < 8; ++j) a[j] = src[PAD(w + j * 512)];
    dft16_zh(a, b);
  } else {
#pragma unroll
    for (int j = 0; j < 16; ++j) a[j] = src[PAD(w + j * 512)];
    dft16(a, b);
  }
  float2 tw = tab[p * S_];
  int ob = q + ((p << 4) * S_);
  dst[PAD(ob)]      = b[0];
  dst[PAD(ob + S_)] = cmul(b[1], tw);
  float2 t2 = cmul(tw, tw);
  float2 we = t2, wo = tw;
#pragma unroll
  for (int m = 1; m <= 7; ++m) {
    dst[PAD(ob + (2*m)   * S_)] = cmul(b[2*m], we);
    wo = cmul(wo, t2);
    dst[PAD(ob + (2*m+1) * S_)] = cmul(b[2*m+1], wo);
    we = cmul(we, t2);
  }
}

// 3 radix-16 stages: A -> B -> A -> B (pre-radix-2 result in B). Ends with sync.
template<bool ZH>
__device__ __forceinline__ void fft_stages16(float2* A, float2* B, const float2* tab, int tid) {
  stage16<1,   0, ZH   >(A, B, tab, tid); __syncthreads();
  stage16<16,  4, false>(B, A, tab, tid); __syncthreads();
  stage16<256, 8, false>(A, B, tab, tid); __syncthreads();
}

// pack(u,v) for PQ: u = V at bin, v = V at mirror bin (both complex spectra of packed pair)
__device__ __forceinline__ float4 pq_pack(float2 u, float2 v) {
  float2 vc = conjf2(v);
  float2 Sm = cadd(u, vc), Dv = csub(u, vc);
  return make_float4(0.25f*(Sm.x + Dv.y), 0.25f*(Sm.y - Dv.x),
                     0.25f*(Sm.x - Dv.y), 0.25f*(Sm.y + Dv.x));
}

// --------------------- kernel 0a: hidden MLP layers ------------------------
__global__ __launch_bounds__(128)
void k_hidden(const float* __restrict__ w_in,  const float* __restrict__ b_in,
              const float* __restrict__ w_hid, const float* __restrict__ b_hid) {
  extern __shared__ __align__(16) char sraw[];
  float* sWh = (float*)sraw;              // 12288 floats
  float* sG  = sWh + 12288;               // 4 warps * 8 pos * 68

  int tid = threadIdx.x;
  for (int i = tid; i < 3072; i += 128)
    ((float4*)sWh)[i] = ((const float4*)w_hid)[i];
  __syncthreads();

  int warp = tid >> 5, lane = tid & 31;
  float* gW = sG + warp * (8 * 68);
  int t0 = (blockIdx.x * 4 + warp) * 8;

  float wi0 = w_in[lane], wi1 = w_in[lane + 32];
  float bi0 = b_in[lane], bi1 = b_in[lane + 32];

  float h0[8], h1[8];
#pragma unroll
  for (int p = 0; p < 8; ++p) {
    int t = t0 + p;
    float idxv;
    if (t == 0 || t == 4096) idxv = 1.0f;
    else if (t < 4096)       idxv = 1.0f / (float)(t + 1);
    else                     idxv = -1.0f / (float)(8193 - t);
    h0[p] = fmaf(idxv, wi0, bi0);
    h1[p] = fmaf(idxv, wi1, bi1);
  }

  for (int l = 0; l < 3; ++l) {
    float ss[8];
#pragma unroll
    for (int p = 0; p < 8; ++p) ss[p] = h0[p]*h0[p] + h1[p]*h1[p];
#pragma unroll
    for (int off = 16; off; off >>= 1)
#pragma unroll
      for (int p = 0; p < 8; ++p) ss[p] += __shfl_xor_sync(0xffffffffu, ss[p], off);
#pragma unroll
    for (int p = 0; p < 8; ++p) {
      float sc = rsqrtf(ss[p] * (1.0f/64.0f) + 1e-8f);
      gW[p*68 + lane]      = fmaxf(h0[p] * sc, 0.0f);
      gW[p*68 + lane + 32] = fmaxf(h1[p] * sc, 0.0f);
    }
    __syncwarp();

    float a0[8], a1[8];
    float bh0 = b_hid[l*64 + lane], bh1 = b_hid[l*64 + lane + 32];
#pragma unroll
    for (int p = 0; p < 8; ++p) { a0[p] = bh0; a1[p] = bh1; }
    const float* Wl = sWh + l * 4096;
    for (int i4 = 0; i4 < 16; ++i4) {
      float4 gv[8];
#pragma unroll
      for (int p = 0; p < 8; ++p) gv[p] = *(const float4*)&gW[p*68 + i4*4];
#pragma unroll
      for (int kk = 0; kk < 4; ++kk) {
        int i = i4*4 + kk;
        float wa = Wl[i*64 + lane], wb = Wl[i*64 + lane + 32];
#pragma unroll
        for (int p = 0; p < 8; ++p) {
          float g = (kk == 0) ? gv[p].x : (kk == 1) ? gv[p].y : (kk == 2) ? gv[p].z : gv[p].w;
          a0[p] = fmaf(g, wa, a0[p]);
          a1[p] = fmaf(g, wb, a1[p]);
        }
      }
    }
#pragma unroll
    for (int p = 0; p < 8; ++p) { h0[p] = a0[p]; h1[p] = a1[p]; }
    __syncwarp();
  }

  float ss[8];
#pragma unroll
  for (int p = 0; p < 8; ++p) ss[p] = h0[p]*h0[p] + h1[p]*h1[p];
#pragma unroll
  for (int off = 16; off; off >>= 1)
#pragma unroll
    for (int p = 0; p < 8; ++p) ss[p] += __shfl_xor_sync(0xffffffffu, ss[p], off);
#pragma unroll
  for (int p = 0; p < 8; ++p) {
    float sc = rsqrtf(ss[p] * (1.0f/64.0f) + 1e-8f);
    g_G[(size_t)(t0 + p)*64 + lane]      = fmaxf(h0[p] * sc, 0.0f);
    g_G[(size_t)(t0 + p)*64 + lane + 32] = fmaxf(h1[p] * sc, 0.0f);
  }
}

// --------------------- kernel 0b: output GEMM (f32x2) ----------------------
__global__ __launch_bounds__(256)
void k_out(const float* __restrict__ w_out, const float* __restrict__ b_out) {
  extern __shared__ __align__(16) char sraw[];
  float* Gs = (float*)sraw;       // 128 x 64, XOR-swizzled float4 columns
  float* Ws = Gs + 128*64;        // 64 x 128

  int tid = threadIdx.x;
  int T0 = blockIdx.x * 128;
  int C0 = blockIdx.y * 128;

  for (int i = tid; i < 128*16; i += 256) {
    int p = i >> 4, kq = i & 15;
    float4 v = *(const float4*)&g_G[(size_t)(T0 + p)*64 + kq*4];
    int sw = (kq ^ (p >> 3)) & 15;
    *(float4*)&Gs[p*64 + sw*4] = v;
  }
  for (int i = tid; i < 64*32; i += 256) {
    int k = i >> 5, cq = i & 31;
    *(float4*)&Ws[k*128 + cq*4] = *(const float4*)&w_out[(size_t)k*512 + C0 + cq*4];
  }
  __syncthreads();

  int pb  = (tid & 15) * 8;
  int cb  = (tid >> 4) * 8;
  int swb = tid & 15;

  u64 acc[4][8];
  {
    float4 bA = *(const float4*)&b_out[C0 + cb];
    float4 bB = *(const float4*)&b_out[C0 + cb + 4];
    u64 b01 = f2pack(bA.x, bA.y), b23 = f2pack(bA.z, bA.w);
    u64 b45 = f2pack(bB.x, bB.y), b67 = f2pack(bB.z, bB.w);
#pragma unroll
    for (int p = 0; p < 8; ++p) { acc[0][p]=b01; acc[1][p]=b23; acc[2][p]=b45; acc[3][p]=b67; }
  }

  for (int k4 = 0; k4 < 16; ++k4) {
    float4 gq[8];
    int col = ((k4 ^ swb) & 15) * 4;
#pragma unroll
    for (int p = 0; p < 8; ++p) gq[p] = *(const float4*)&Gs[(pb + p)*64 + col];
#pragma unroll
    for (int kk = 0; kk < 4; ++kk) {
      const float* wr = &Ws[(k4*4 + kk)*128 + cb];
      float4 wA = *(const float4*)wr;
      float4 wB = *(const float4*)(wr + 4);
      u64 w01 = f2pack(wA.x, wA.y), w23 = f2pack(wA.z, wA.w);
      u64 w45 = f2pack(wB.x, wB.y), w67 = f2pack(wB.z, wB.w);
#pragma unroll
      for (int p = 0; p < 8; ++p) {
        float g = (kk == 0) ? gq[p].x : (kk == 1) ? gq[p].y : (kk == 2) ? gq[p].z : gq[p].w;
        u64 gs = f2pack(g, g);
        acc[0][p] = f2fma(gs, w01, acc[0][p]);
        acc[1][p] = f2fma(gs, w23, acc[1][p]);
        acc[2][p] = f2fma(gs, w45, acc[2][p]);
        acc[3][p] = f2fma(gs, w67, acc[3][p]);
      }
    }
  }

#pragma unroll
  for (int cp = 0; cp < 4; ++cp) {
    float2 u[8];
#pragma unroll
    for (int p = 0; p < 8; ++p) u[p] = f2unpack(acc[cp][p]);
    size_t row0 = (size_t)(C0 + cb + 2*cp) * MM + T0 + pb;
    *(float4*)&g_A[row0]     = make_float4(u[0].x, u[1].x, u[2].x, u[3].x);
    *(float4*)&g_A[row0 + 4] = make_float4(u[4].x, u[5].x, u[6].x, u[7].x);
    size_t row1 = row0 + MM;
    *(float4*)&g_A[row1]     = make_float4(u[0].y, u[1].y, u[2].y, u[3].y);
    *(float4*)&g_A[row1 + 4] = make_float4(u[4].y, u[5].y, u[6].y, u[7].y);
  }
}

// --------------------- kernel 1: FFT of a, build P/Q -----------------------
// fused final radix-2 + PQ build: quadruple {k, 4096-k, 4096+k, 8192-k}
__global__ __launch_bounds__(512, 1)
void k_afft() {
  extern __shared__ __align__(16) char sraw[];
  float2* A   = (float2*)sraw;
  float2* B   = A + FBUF;
  float2* tab = B + FBUF;
  int tid = threadIdx.x;
  int h  = blockIdx.x >> 5;
  int dp = blockIdx.x & 31;

  const float* r0 = g_A + (size_t)(h * 64 + dp * 2) * MM;
  const float* r1 = r0 + MM;
  for (int t = tid; t < MM; t += 512) A[PAD(t)] = make_float2(r0[t], r1[t]);
  {
    float s, c; sincospif(-(float)tid * (1.0f/4096.0f), &s, &c);
    tab[tid] = make_float2(c, s);
  }
  __syncthreads();
  fft_stages16<false>(A, B, tab, tid);           // pre-radix-2 spectrum in B

  float4* pq = g_PQ + (size_t)(h * 32 + dp) * MM;
#pragma unroll
  for (int it = 0; it < 4; ++it) {
    int k = tid + it * 512;
    if (k == 0) {
      float2 f0 = B[PAD(0)], f1 = B[PAD(4096)];
      float2 Z0 = cadd(f0, f1), Z4 = csub(f0, f1);
      pq[0]    = pq_pack(Z0, Z0);
      pq[4096] = pq_pack(Z4, Z4);
      float2 g0 = B[PAD(2048)], g1 = B[PAD(6144)];
      float2 Z2 = cadd(g0, g1), Z6 = csub(g0, g1);
      pq[2048] = pq_pack(Z2, Z6);
      pq[6144] = pq_pack(Z6, Z2);
    } else {
      float2 f0 = B[PAD(k)],        f1 = B[PAD(k + 4096)];
      float2 g0 = B[PAD(4096 - k)], g1 = B[PAD(8192 - k)];
      float2 Zk  = cadd(f0, f1), Zk4 = csub(f0, f1);   // Z[k], Z[k+4096]
      float2 Zm4 = cadd(g0, g1), Zm  = csub(g0, g1);   // Z[4096-k], Z[8192-k]
      pq[k]        = pq_pack(Zk,  Zm );
      pq[8192 - k] = pq_pack(Zm,  Zk );
      pq[4096 - k] = pq_pack(Zm4, Zk4);
      pq[4096 + k] = pq_pack(Zk4, Zm4);
    }
  }
}

// ----------------- kernel 2: FFT conv per (b, h, dpair) --------------------
__global__ __launch_bounds__(512, 1)
void k_conv(const float* __restrict__ x, float* __restrict__ out) {
  extern __shared__ __align__(16) char sraw[];
  float2* A   = (float2*)sraw;
  float2* B   = A + FBUF;
  float2* tab = B + FBUF;
  int tid = threadIdx.x;
  int b   = blockIdx.x >> 8;
  int rem = blockIdx.x & 255;
  int h   = rem >> 5;
  int dp  = rem & 31;

  const float* xb = x + ((size_t)(b * 8 + h) * NSEQ) * 64 + dp * 2;
  for (int j = tid; j < NSEQ; j += 512)
    A[PAD(j)] = *(const float2*)(xb + (size_t)j * 64);
  {
    float s, c; sincospif(-(float)tid * (1.0f/4096.0f), &s, &c);
    tab[tid] = make_float2(c, s);
  }
  __syncthreads();

  fft_stages16<true>(A, B, tab, tid);            // forward, pre-radix-2 Z' in B

  // fused: final radix-2 + pointwise (W = P*Z + Q*conj(Z_mirror)) + conj -> A
  const float4* pq = g_PQ + (size_t)(h * 32 + dp) * MM;
#pragma unroll
  for (int it = 0; it < 4; ++it) {
    int k = tid + it * 512;
    if (k == 0) {
      float2 f0 = B[PAD(0)], f1 = B[PAD(4096)];
      float2 Z0 = cadd(f0, f1), Z4 = csub(f0, f1);
      float4 c0 = pq[0], c4 = pq[4096];
      float2 W0 = cadd(cmul(make_float2(c0.x,c0.y), Z0), cmul(make_float2(c0.z,c0.w), conjf2(Z0)));
      float2 W4 = cadd(cmul(make_float2(c4.x,c4.y), Z4), cmul(make_float2(c4.z,c4.w), conjf2(Z4)));
      A[PAD(0)]    = conjf2(W0);
      A[PAD(4096)] = conjf2(W4);
      float2 g0 = B[PAD(2048)], g1 = B[PAD(6144)];
      float2 Z2 = cadd(g0, g1), Z6 = csub(g0, g1);
      float4 c2 = pq[2048], c6 = pq[6144];
      float2 W2 = cadd(cmul(make_float2(c2.x,c2.y), Z2), cmul(make_float2(c2.z,c2.w), conjf2(Z6)));
      float2 W6 = cadd(cmul(make_float2(c6.x,c6.y), Z6), cmul(make_float2(c6.z,c6.w), conjf2(Z2)));
      A[PAD(2048)] = conjf2(W2);
      A[PAD(6144)] = conjf2(W6);
    } else {
      float2 f0 = B[PAD(k)],        f1 = B[PAD(k + 4096)];
      float2 g0 = B[PAD(4096 - k)], g1 = B[PAD(8192 - k)];
      float2 Zk  = cadd(f0, f1), Zk4 = csub(f0, f1);   // Z[k], Z[4096+k]
      float2 Zm4 = cadd(g0, g1), Zm  = csub(g0, g1);   // Z[4096-k], Z[8192-k]
      float4 cK = pq[k], cM = pq[8192 - k], cA = pq[4096 - k], cB = pq[4096 + k];
      float2 Wk  = cadd(cmul(make_float2(cK.x,cK.y), Zk ), cmul(make_float2(cK.z,cK.w), conjf2(Zm )));
      float2 Wm  = cadd(cmul(make_float2(cM.x,cM.y), Zm ), cmul(make_float2(cM.z,cM.w), conjf2(Zk )));
      float2 Wa  = cadd(cmul(make_float2(cA.x,cA.y), Zm4), cmul(make_float2(cA.z,cA.w), conjf2(Zk4)));
      float2 Wb  = cadd(cmul(make_float2(cB.x,cB.y), Zk4), cmul(make_float2(cB.z,cB.w), conjf2(Zm4)));
      A[PAD(k)]        = conjf2(Wk);
      A[PAD(8192 - k)] = conjf2(Wm);
      A[PAD(4096 - k)] = conjf2(Wa);
      A[PAD(4096 + k)] = conjf2(Wb);
    }
  }
  __syncthreads();

  fft_stages16<false>(A, B, tab, tid);           // inverse stages, pre-radix-2 in B

  // fused final radix-2 + output (only lower 4096 needed), ifft = conj(.)/M
  float* ob = out + ((size_t)(b * 8 + h) * NSEQ) * 64 + dp * 2;
  const float inv = 1.0f / (float)MM;
#pragma unroll
  for (int it = 0; it < 8; ++it) {
    int w = tid + it * 512;
    float2 s = cadd(B[PAD(w)], B[PAD(w + 4096)]);
    *(float2*)(ob + (size_t)w * 64) = make_float2(s.x * inv, -s.y * inv);
  }
}

// ------------------------------ launch -------------------------------------
extern "C" void kernel_launch(void* const* d_in, const int* in_sizes, int n_in,
                              void* d_out, int out_size) {
  const float* x     = (const float*)d_in[0];
  const float* w_in  = (const float*)d_in[1];
  const float* b_in  = (const float*)d_in[2];
  const float* w_hid = (const float*)d_in[3];
  const float* b_hid = (const float*)d_in[4];
  const float* w_out = (const float*)d_in[5];
  const float* b_out = (const float*)d_in[6];
  float* out = (float*)d_out;

  const size_t smemH = (size_t)(12288 + 4 * 8 * 68) * sizeof(float);      //  57,856 B
  const size_t smemO = (size_t)(128*64 + 64*128) * sizeof(float);         //  65,536 B
  const size_t smemF = (size_t)(2 * FBUF + 512) * sizeof(float2);         // 143,360 B
  cudaFuncSetAttribute(k_hidden, cudaFuncAttributeMaxDynamicSharedMemorySize, (int)smemH);
  cudaFuncSetAttribute(k_out,    cudaFuncAttributeMaxDynamicSharedMemorySize, (int)smemO);
  cudaFuncSetAttribute(k_afft,   cudaFuncAttributeMaxDynamicSharedMemorySize, (int)smemF);
  cudaFuncSetAttribute(k_conv,   cudaFuncAttributeMaxDynamicSharedMemorySize, (int)smemF);

  k_hidden<<<256, 128, smemH>>>(w_in, b_in, w_hid, b_hid);
  k_out   <<<dim3(64, 4), 256, smemO>>>(w_out, b_out);
  k_afft  <<<256, 512, smemF>>>();
  k_conv  <<<512, 512, smemF>>>(x, out);
}